// round 7
// baseline (speedup 1.0000x reference)
#include <cuda_runtime.h>
#include <cstdint>

// Causal unbiased-EMA instance norm, x: [B=8, C=256, T=16384] fp32 — EXACT
// via per-lane affine prefix scan, software-pipelined over 4 time-tiles.
//
//   s1 = a*s1 + (1-a)*x ; s2 = a*s2 + (1-a)*x^2 ; w = a*w + (1-a)
//   y  = (w*x - s1) * rsqrt(max(w*s2 - s1^2, 0) + eps*w^2)
//
// One block per (b,c) lane, 256 threads. The lane is processed as 4 tiles of
// 4096; all cp.async loads are issued upfront in 4 commit groups, so tiles
// 1..3 stream from DRAM while tile 0 computes. Each tile does: 16-step
// per-thread local EMA sums -> affine scan (decay a^16) composed onto a
// carry state from previous tiles -> 16-step normalize -> coalesced store.

#define T_LEN  16384
#define TPB    256
#define NWARP  (TPB / 32)        // 8
#define NTILE  4
#define TILE   (T_LEN / NTILE)   // 4096
#define KP     (TILE / TPB)      // 16 steps per thread per tile

#define ALPHA_F 0.99f
#define OMA_F   0.01f
#define EPS_F   1e-5f
#define A16_F   0.85145777f      // 0.99^16

#define PAD(i)  ((i) + (((i) >> 5) << 2))      // +4 floats (16B) per 32-row
#define SMEM_F  (T_LEN + ((T_LEN >> 5) << 2))  // 18432 floats = 73728 B

__device__ __forceinline__ void cp_async16(float* smem_dst, const float* gmem_src) {
    uint32_t s = (uint32_t)__cvta_generic_to_shared(smem_dst);
    asm volatile("cp.async.cg.shared.global [%0], [%1], 16;" :: "r"(s), "l"(gmem_src));
}

__device__ __forceinline__ void cp_wait(int t) {
    switch (t) {                 // wait until at most (NTILE-1-t) groups pending
        case 0: asm volatile("cp.async.wait_group 3;" ::: "memory"); break;
        case 1: asm volatile("cp.async.wait_group 2;" ::: "memory"); break;
        case 2: asm volatile("cp.async.wait_group 1;" ::: "memory"); break;
        default: asm volatile("cp.async.wait_group 0;" ::: "memory"); break;
    }
}

__device__ __forceinline__ void warm_step(float xi, float& s1, float& s2) {
    float t = OMA_F * xi;
    s1 = fmaf(ALPHA_F, s1, t);
    s2 = fmaf(ALPHA_F, s2, t * xi);
}

__device__ __forceinline__ float ema_step(float xi, float& s1, float& s2, float& w) {
    float t = OMA_F * xi;
    s1 = fmaf(ALPHA_F, s1, t);
    s2 = fmaf(ALPHA_F, s2, t * xi);
    w  = fmaf(ALPHA_F, w, OMA_F);
    float num   = fmaf(w, xi, -s1);
    float dcore = fmaf(w, s2, -(s1 * s1));
    dcore = fmaxf(dcore, 0.0f);               // t=1 cancellation guard (NaN-proof)
    float d = fmaf(EPS_F, w * w, dcore);
    float r;
    asm("rsqrt.approx.f32 %0, %1;" : "=f"(r) : "f"(d));
    return num * r;
}

extern __shared__ float s_buf[];

__global__ void __launch_bounds__(TPB)
ema_norm_kernel(const float* __restrict__ x, float* __restrict__ y)
{
    __shared__ float tv1[NWARP], tv2[NWARP], tm[NWARP];

    const int tid  = threadIdx.x;
    const int lane = tid & 31;
    const int wid  = tid >> 5;
    const size_t base = (size_t)blockIdx.x * T_LEN;

    // ---- issue ALL loads upfront, one commit group per tile ----
    #pragma unroll
    for (int t = 0; t < NTILE; t++) {
        #pragma unroll
        for (int k = 0; k < TILE / (TPB * 4); k++) {
            int i4 = t * TILE + k * (TPB * 4) + 4 * tid;   // 16B aligned
            cp_async16(s_buf + PAD(i4), x + base + i4);
        }
        asm volatile("cp.async.commit_group;");
    }

    float c1 = 0.f, c2 = 0.f, cm = 1.f;       // affine carry across tiles

    #pragma unroll
    for (int t = 0; t < NTILE; t++) {
        cp_wait(t);
        __syncthreads();

        // ---- pass 1: 16-step local EMA sums from zero state (LDS.128) ----
        const int t0 = t * TILE + tid * KP;
        const float4* row = reinterpret_cast<const float4*>(s_buf + PAD(t0));
        float L1 = 0.f, L2 = 0.f;
        #pragma unroll
        for (int i = 0; i < KP / 4; i++) {
            float4 v = row[i];
            warm_step(v.x, L1, L2);
            warm_step(v.y, L1, L2);
            warm_step(v.z, L1, L2);
            warm_step(v.w, L1, L2);
        }

        // ---- in-warp affine inclusive scan: combine = vR + mR*vL ----
        float v1 = L1, v2 = L2, m = A16_F;
        #pragma unroll
        for (int d = 1; d < 32; d <<= 1) {
            float pv1 = __shfl_up_sync(0xffffffffu, v1, d);
            float pv2 = __shfl_up_sync(0xffffffffu, v2, d);
            float pm  = __shfl_up_sync(0xffffffffu, m,  d);
            if (lane >= d) {
                v1 = fmaf(m, pv1, v1);
                v2 = fmaf(m, pv2, v2);
                m *= pm;
            }
        }
        float ev1 = __shfl_up_sync(0xffffffffu, v1, 1);
        float ev2 = __shfl_up_sync(0xffffffffu, v2, 1);
        float em  = __shfl_up_sync(0xffffffffu, m,  1);
        if (lane == 0) { ev1 = 0.f; ev2 = 0.f; em = 1.f; }

        if (lane == 31) { tv1[wid] = v1; tv2[wid] = v2; tm[wid] = m; }
        __syncthreads();

        // cross-warp exclusive prefix (j < wid) and full-tile total (all j)
        float p1 = 0.f, p2 = 0.f, pm = 1.f;
        float T1 = 0.f, T2 = 0.f, TM = 1.f;
        #pragma unroll
        for (int j = 0; j < NWARP; j++) {
            float a1 = tv1[j], a2 = tv2[j], am = tm[j];
            if (j < wid) {
                p1 = fmaf(am, p1, a1);
                p2 = fmaf(am, p2, a2);
                pm *= am;
            }
            T1 = fmaf(am, T1, a1);
            T2 = fmaf(am, T2, a2);
            TM *= am;
        }

        // thread's exact start state = local-exclusive-prefix ∘ carry
        float EM = em * pm;                    // local exclusive multiplier
        float s1 = fmaf(em, p1, ev1);
        float s2 = fmaf(em, p2, ev2);
        s1 = fmaf(EM, c1, s1);
        s2 = fmaf(EM, c2, s2);
        float w = 1.0f - EM * cm;              // 1 - alpha^{t0}

        // advance carry by this tile's total (uses OLD carry)
        float nc1 = fmaf(TM, c1, T1);
        float nc2 = fmaf(TM, c2, T2);
        cm *= TM;
        c1 = nc1; c2 = nc2;

        // ---- pass 2: normalize 16 steps from exact state, in-place ----
        float4* rw = reinterpret_cast<float4*>(s_buf + PAD(t0));
        #pragma unroll
        for (int i = 0; i < KP / 4; i++) {
            float4 v = rw[i];
            float4 o;
            o.x = ema_step(v.x, s1, s2, w);
            o.y = ema_step(v.y, s1, s2, w);
            o.z = ema_step(v.z, s1, s2, w);
            o.w = ema_step(v.w, s1, s2, w);
            rw[i] = o;
        }
        __syncthreads();

        // ---- coalesced vector store of this tile ----
        #pragma unroll
        for (int k = 0; k < TILE / (TPB * 4); k++) {
            int i4 = t * TILE + k * (TPB * 4) + 4 * tid;
            float4 v = *reinterpret_cast<const float4*>(s_buf + PAD(i4));
            *reinterpret_cast<float4*>(y + base + i4) = v;
        }
    }
}

extern "C" void kernel_launch(void* const* d_in, const int* in_sizes, int n_in,
                              void* d_out, int out_size) {
    const float* x = (const float*)d_in[0];
    float*       y = (float*)d_out;

    int total = in_sizes[0];            // B*C*T
    int lanes = total / T_LEN;          // 2048 blocks, one per lane

    cudaFuncSetAttribute(ema_norm_kernel,
                         cudaFuncAttributeMaxDynamicSharedMemorySize,
                         SMEM_F * sizeof(float));
    ema_norm_kernel<<<lanes, TPB, SMEM_F * sizeof(float)>>>(x, y);
}

// round 9
// speedup vs baseline: 1.0357x; 1.0357x over previous
#include <cuda_runtime.h>
#include <cstdint>

// Causal unbiased-EMA instance norm, x: [B=8, C=256, T=16384] fp32.
//   s1 = a*s1 + (1-a)*x ; s2 = a*s2 + (1-a)*x^2 ; w = a*w + (1-a)  (= 1-a^t)
//   y  = (w*x - s1) * rsqrt(max(w*s2 - s1^2, 0) + eps*w^2)
//
// R9: one block per HALF lane (grid 4096, 256 thr, ~40KB smem -> 5 blocks/SM)
// for finer inter-block phase interleaving. Even halves: exact affine scan
// from zero state (KP=32). Odd halves: 1024-element warm-up folded into the
// scan (tile 9216, KP=36); carry multiplier a^7168 keeps w exact; state
// truncation a^1024 = 3.4e-5 is far inside the 1e-3 tolerance.
//
// R8 bug fixed: smem padding granularity now matches KP (i + 4*(i/KP)), so
// the per-thread KP-float sweep is linear within a padded row for BOTH
// tile shapes. 36 % 4 == 0 keeps float4 alignment; all copy loops use the
// same PAD so the layout is consistent.

#define T_LEN   16384
#define HALF_N  8192
#define TPB     256
#define NWARP   8

#define ALPHA_F 0.99f
#define OMA_F   0.01f
#define EPS_F   1e-5f
#define A32_F   0.72498034f     // 0.99^32
#define A36_F   0.69641322f     // 0.99^36
#define CM_ODD  5.16502e-32f    // 0.99^7168 (warm start offset of odd half)

#define SMEM_FLOATS 10240       // odd tile: 9216 + 4*(9216/36) = 10240 (40KB)

__device__ __forceinline__ void cp_async16(float* smem_dst, const float* gmem_src) {
    uint32_t s = (uint32_t)__cvta_generic_to_shared(smem_dst);
    asm volatile("cp.async.cg.shared.global [%0], [%1], 16;" :: "r"(s), "l"(gmem_src));
}

__device__ __forceinline__ void warm_step(float xi, float& s1, float& s2) {
    float t = OMA_F * xi;
    s1 = fmaf(ALPHA_F, s1, t);
    s2 = fmaf(ALPHA_F, s2, t * xi);
}

__device__ __forceinline__ float ema_step(float xi, float& s1, float& s2, float& w) {
    float t = OMA_F * xi;
    s1 = fmaf(ALPHA_F, s1, t);
    s2 = fmaf(ALPHA_F, s2, t * xi);
    w  = fmaf(ALPHA_F, w, OMA_F);
    float num   = fmaf(w, xi, -s1);
    float dcore = fmaf(w, s2, -(s1 * s1));
    dcore = fmaxf(dcore, 0.0f);               // t=1 cancellation guard (NaN-proof)
    float d = fmaf(EPS_F, w * w, dcore);
    float r;
    asm("rsqrt.approx.f32 %0, %1;" : "=f"(r) : "f"(d));
    return num * r;
}

extern __shared__ float s_buf[];

// WARM = 0 (even half, KP=32) or 1024 (odd half, KP=36).
template<int WARM>
__device__ __forceinline__ void process_half(
    const float* __restrict__ x, float* __restrict__ y,
    float* tv1, float* tv2, float* tm)
{
    constexpr int TILE_N = HALF_N + WARM;          // 8192 / 9216
    constexpr int KP     = TILE_N / TPB;           // 32 / 36
    const float ASEG     = (WARM ? A36_F : A32_F); // a^KP
    const float CM0      = (WARM ? CM_ODD : 1.0f);

    // pad: +4 floats per KP-float row (layout-consistent for all loops)
    auto PAD = [](int i) constexpr -> int {
        return i + (((unsigned)i / (unsigned)KP) << 2);
    };

    const int tid  = threadIdx.x;
    const int lane = tid & 31;
    const int wid  = tid >> 5;
    const int half = blockIdx.x & 1;
    const size_t lane_base = (size_t)(blockIdx.x >> 1) * T_LEN;
    const size_t in_base   = lane_base + (size_t)half * HALF_N - WARM;
    const size_t out_base  = lane_base + (size_t)half * HALF_N;

    // ---- coalesced async load of the tile ----
    #pragma unroll
    for (int k = 0; k < TILE_N / (TPB * 4); k++) {
        int i4 = 4 * tid + k * (TPB * 4);          // multiple of 4
        cp_async16(s_buf + PAD(i4), x + in_base + i4);
    }
    asm volatile("cp.async.commit_group;");
    asm volatile("cp.async.wait_group 0;" ::: "memory");
    __syncthreads();

    // ---- pass 1: KP-step local EMA sums from zero state (LDS.128) ----
    const int t0 = tid * KP;
    const float4* row = reinterpret_cast<const float4*>(s_buf + PAD(t0));
    float L1 = 0.f, L2 = 0.f;
    #pragma unroll
    for (int i = 0; i < KP / 4; i++) {
        float4 v = row[i];
        warm_step(v.x, L1, L2);
        warm_step(v.y, L1, L2);
        warm_step(v.z, L1, L2);
        warm_step(v.w, L1, L2);
    }

    // ---- in-warp affine inclusive scan: combine = vR + mR*vL ----
    float v1 = L1, v2 = L2, m = ASEG;
    #pragma unroll
    for (int d = 1; d < 32; d <<= 1) {
        float pv1 = __shfl_up_sync(0xffffffffu, v1, d);
        float pv2 = __shfl_up_sync(0xffffffffu, v2, d);
        float pm  = __shfl_up_sync(0xffffffffu, m,  d);
        if (lane >= d) {
            v1 = fmaf(m, pv1, v1);
            v2 = fmaf(m, pv2, v2);
            m *= pm;
        }
    }
    float ev1 = __shfl_up_sync(0xffffffffu, v1, 1);
    float ev2 = __shfl_up_sync(0xffffffffu, v2, 1);
    float em  = __shfl_up_sync(0xffffffffu, m,  1);
    if (lane == 0) { ev1 = 0.f; ev2 = 0.f; em = 1.f; }

    if (lane == 31) { tv1[wid] = v1; tv2[wid] = v2; tm[wid] = m; }
    __syncthreads();
    float p1 = 0.f, p2 = 0.f, pm = 1.f;
    for (int j = 0; j < wid; j++) {                // oldest-first composition
        p1 = fmaf(tm[j], p1, tv1[j]);
        p2 = fmaf(tm[j], p2, tv2[j]);
        pm *= tm[j];
    }
    float s1 = fmaf(em, p1, ev1);                  // exact local start state
    float s2 = fmaf(em, p2, ev2);
    float w  = 1.0f - (em * pm) * CM0;             // 1 - a^{t_global}

    // ---- pass 2: normalize KP steps from start state, in-place ----
    float4* rw = reinterpret_cast<float4*>(s_buf + PAD(t0));
    #pragma unroll
    for (int i = 0; i < KP / 4; i++) {
        float4 v = rw[i];
        float4 o;
        o.x = ema_step(v.x, s1, s2, w);
        o.y = ema_step(v.y, s1, s2, w);
        o.z = ema_step(v.z, s1, s2, w);
        o.w = ema_step(v.w, s1, s2, w);
        rw[i] = o;
    }
    __syncthreads();

    // ---- coalesced vector store of output region [WARM, TILE_N) ----
    #pragma unroll
    for (int k = 0; k < HALF_N / (TPB * 4); k++) {
        int idx = WARM + 4 * tid + k * (TPB * 4);  // multiple of 4
        float4 v = *reinterpret_cast<const float4*>(s_buf + PAD(idx));
        *reinterpret_cast<float4*>(y + out_base + (idx - WARM)) = v;
    }
}

__global__ void __launch_bounds__(TPB)
ema_norm_kernel(const float* __restrict__ x, float* __restrict__ y)
{
    __shared__ float tv1[NWARP], tv2[NWARP], tm[NWARP];
    if (blockIdx.x & 1)
        process_half<1024>(x, y, tv1, tv2, tm);    // odd half: warm-up in scan
    else
        process_half<0>(x, y, tv1, tv2, tm);       // even half: exact from t=0
}

extern "C" void kernel_launch(void* const* d_in, const int* in_sizes, int n_in,
                              void* d_out, int out_size) {
    const float* x = (const float*)d_in[0];
    float*       y = (float*)d_out;

    int total = in_sizes[0];            // B*C*T
    int lanes = total / T_LEN;          // 2048
    int grid  = lanes * 2;              // one block per half-lane

    cudaFuncSetAttribute(ema_norm_kernel,
                         cudaFuncAttributeMaxDynamicSharedMemorySize,
                         SMEM_FLOATS * sizeof(float));
    ema_norm_kernel<<<grid, TPB, SMEM_FLOATS * sizeof(float)>>>(x, y);
}

// round 11
// speedup vs baseline: 1.0754x; 1.0383x over previous
#include <cuda_runtime.h>
#include <cstdint>

// Causal unbiased-EMA instance norm, x: [B=8, C=256, T=16384] fp32 — EXACT
// via per-lane block decomposition + affine prefix scan (R5 structure).
//
//   s1 = a*s1 + (1-a)*x ; s2 = a*s2 + (1-a)*x^2 ; w = a*w + (1-a)  (= 1-a^t)
//   y  = (w*x - s1) * rsqrt(w*s2 + eps*w^2 - s1^2)   [floored at 1e-10]
//
// R11 = R10 with the apow() constexpr marked __host__ __device__ (compile fix).
// Instruction diet vs R5:
//  * pass 1 uses the closed form  L1 = sum 0.01*a^(KP-1-i)*x_i  (compile-time
//    weights -> immediate-form FFMA, no serial chain, 3 inst/elem).
//  * threads whose start time t0 >= 1792 have w == 1.0f exactly in fp32
//    (matching the reference's saturated iteration), so 89% of threads run a
//    simplified 10-inst step with no w update.

#define T_LEN  16384
#define TPB    256
#define KP     (T_LEN / TPB)     // 64 steps per thread
#define NWARP  (TPB / 32)

#define ALPHA_F 0.99f
#define OMA_F   0.01f
#define EPS_F   1e-5f
#define A64_F   0.52559649f      // 0.99^64
#define W1_TID  28               // tid >= 28  ->  t0 >= 1792 -> w == 1.0f

#define PAD(i)  ((i) + (((i) >> 6) << 2))      // +4 floats (16B) per 64-row
#define SMEM_F  (T_LEN + ((T_LEN >> 6) << 2))  // 17408 floats = 69632 B

__device__ __forceinline__ void cp_async16(float* smem_dst, const float* gmem_src) {
    uint32_t s = (uint32_t)__cvta_generic_to_shared(smem_dst);
    asm volatile("cp.async.cg.shared.global [%0], [%1], 16;" :: "r"(s), "l"(gmem_src));
}

// compile-time alpha^n (usable in device constexpr context)
__host__ __device__ constexpr float apow(int n) {
    float r = 1.0f;
    for (int i = 0; i < n; i++) r *= ALPHA_F;
    return r;
}

// pass-1 dot product, fully unrolled with constant weights; two accumulator
// pairs for ILP.  c_i = 0.01 * a^(KP-1-i).
template<int I>
__device__ __forceinline__ void warm_unroll(const float4* row,
                                            float& a0, float& b0,
                                            float& a1, float& b1) {
    if constexpr (I < KP / 4) {
        float4 v = row[I];
        constexpr float c0 = OMA_F * apow(KP - 1 - (4 * I + 0));
        constexpr float c1 = OMA_F * apow(KP - 1 - (4 * I + 1));
        constexpr float c2 = OMA_F * apow(KP - 1 - (4 * I + 2));
        constexpr float c3 = OMA_F * apow(KP - 1 - (4 * I + 3));
        float t0 = c0 * v.x;  a0 += t0;  b0 = fmaf(t0, v.x, b0);
        float t1 = c1 * v.y;  a1 += t1;  b1 = fmaf(t1, v.y, b1);
        float t2 = c2 * v.z;  a0 += t2;  b0 = fmaf(t2, v.z, b0);
        float t3 = c3 * v.w;  a1 += t3;  b1 = fmaf(t3, v.w, b1);
        warm_unroll<I + 1>(row, a0, b0, a1, b1);
    }
}

// full step: w still evolving (threads with t0 < 1792)
__device__ __forceinline__ float ema_step_w(float xi, float& s1, float& s2, float& w) {
    float t = OMA_F * xi;
    s1 = fmaf(ALPHA_F, s1, t);
    s2 = fmaf(ALPHA_F, s2, t * xi);
    w  = fmaf(ALPHA_F, w, OMA_F);
    float num = fmaf(w, xi, -s1);
    float e   = fmaf(EPS_F, w, s2);           // s2 + eps*w
    float d   = fmaf(w, e, -(s1 * s1));       // w*s2 + eps*w^2 - s1^2
    d = fmaxf(d, 1e-10f);                     // cancellation guard (NaN-proof)
    float r;
    asm("rsqrt.approx.f32 %0, %1;" : "=f"(r) : "f"(d));
    return num * r;
}

// saturated step: w == 1.0f exactly (matches reference's saturated iteration)
__device__ __forceinline__ float ema_step_1(float xi, float& s1, float& s2) {
    float t = OMA_F * xi;
    s1 = fmaf(ALPHA_F, s1, t);
    s2 = fmaf(ALPHA_F, s2, t * xi);
    float num = xi - s1;
    float e   = s2 + EPS_F;
    float d   = fmaf(-s1, s1, e);
    d = fmaxf(d, 1e-10f);
    float r;
    asm("rsqrt.approx.f32 %0, %1;" : "=f"(r) : "f"(d));
    return num * r;
}

extern __shared__ float s_buf[];

__global__ void __launch_bounds__(TPB)
ema_norm_kernel(const float* __restrict__ x, float* __restrict__ y)
{
    __shared__ float tv1[NWARP], tv2[NWARP], tm[NWARP];

    const int tid  = threadIdx.x;
    const int lane = tid & 31;
    const int wid  = tid >> 5;
    const size_t base = (size_t)blockIdx.x * T_LEN;

    // ---- async vector load: 16 x cp.async.cg of 16B per thread ----
    #pragma unroll
    for (int k = 0; k < T_LEN / (TPB * 4); k++) {
        int i4 = 4 * tid + k * (TPB * 4);     // float index, 16B aligned
        cp_async16(s_buf + PAD(i4), x + base + i4);
    }
    asm volatile("cp.async.commit_group;");
    asm volatile("cp.async.wait_group 0;" ::: "memory");
    __syncthreads();

    // ---- pass 1: constant-weight segment sums (no serial chain) ----
    const int t0 = tid * KP;
    const float4* row = reinterpret_cast<const float4*>(s_buf + PAD(t0));
    float a0 = 0.f, b0 = 0.f, a1 = 0.f, b1 = 0.f;
    warm_unroll<0>(row, a0, b0, a1, b1);
    float L1 = a0 + a1;
    float L2 = b0 + b1;

    // ---- in-warp affine inclusive scan: combine = vR + mR*vL ----
    float v1 = L1, v2 = L2, m = A64_F;
    #pragma unroll
    for (int d = 1; d < 32; d <<= 1) {
        float pv1 = __shfl_up_sync(0xffffffffu, v1, d);
        float pv2 = __shfl_up_sync(0xffffffffu, v2, d);
        float pm  = __shfl_up_sync(0xffffffffu, m,  d);
        if (lane >= d) {
            v1 = fmaf(m, pv1, v1);
            v2 = fmaf(m, pv2, v2);
            m *= pm;
        }
    }
    float ev1 = __shfl_up_sync(0xffffffffu, v1, 1);
    float ev2 = __shfl_up_sync(0xffffffffu, v2, 1);
    float em  = __shfl_up_sync(0xffffffffu, m,  1);
    if (lane == 0) { ev1 = 0.f; ev2 = 0.f; em = 1.f; }

    if (lane == 31) { tv1[wid] = v1; tv2[wid] = v2; tm[wid] = m; }
    __syncthreads();
    float p1 = 0.f, p2 = 0.f, pm = 1.f;
    for (int j = 0; j < wid; j++) {           // oldest-first composition
        p1 = fmaf(tm[j], p1, tv1[j]);
        p2 = fmaf(tm[j], p2, tv2[j]);
        pm *= tm[j];
    }
    float s1 = fmaf(em, p1, ev1);
    float s2 = fmaf(em, p2, ev2);
    float w  = 1.0f - pm * em;                // == 1.0f exactly for tid >= 28

    // ---- pass 2: normalize 64 steps from exact state, in-place ----
    float4* rw = reinterpret_cast<float4*>(s_buf + PAD(t0));
    if (tid >= W1_TID) {
        #pragma unroll
        for (int i = 0; i < KP / 4; i++) {
            float4 v = rw[i];
            float4 o;
            o.x = ema_step_1(v.x, s1, s2);
            o.y = ema_step_1(v.y, s1, s2);
            o.z = ema_step_1(v.z, s1, s2);
            o.w = ema_step_1(v.w, s1, s2);
            rw[i] = o;
        }
    } else {
        #pragma unroll
        for (int i = 0; i < KP / 4; i++) {
            float4 v = rw[i];
            float4 o;
            o.x = ema_step_w(v.x, s1, s2, w);
            o.y = ema_step_w(v.y, s1, s2, w);
            o.z = ema_step_w(v.z, s1, s2, w);
            o.w = ema_step_w(v.w, s1, s2, w);
            rw[i] = o;
        }
    }
    __syncthreads();

    // ---- vector store: LDS.128 + STG.128, coalesced ----
    #pragma unroll
    for (int k = 0; k < T_LEN / (TPB * 4); k++) {
        int i4 = 4 * tid + k * (TPB * 4);
        float4 v = *reinterpret_cast<const float4*>(s_buf + PAD(i4));
        *reinterpret_cast<float4*>(y + base + i4) = v;
    }
}

extern "C" void kernel_launch(void* const* d_in, const int* in_sizes, int n_in,
                              void* d_out, int out_size) {
    const float* x = (const float*)d_in[0];
    float*       y = (float*)d_out;

    int total = in_sizes[0];            // B*C*T
    int lanes = total / T_LEN;          // 2048 blocks, one per lane

    cudaFuncSetAttribute(ema_norm_kernel,
                         cudaFuncAttributeMaxDynamicSharedMemorySize,
                         SMEM_F * sizeof(float));
    ema_norm_kernel<<<lanes, TPB, SMEM_F * sizeof(float)>>>(x, y);
}

// round 12
// speedup vs baseline: 1.1695x; 1.0874x over previous
#include <cuda_runtime.h>
#include <cstdint>

// Causal unbiased-EMA instance norm, x: [B=8, C=256, T=16384] fp32 — EXACT
// via per-lane affine prefix scan, warp-autonomous dataflow.
//
//   s1 = a*s1 + (1-a)*x ; s2 = a*s2 + (1-a)*x^2 ; w = a*w + (1-a)  (= 1-a^t)
//   y  = (w*x - s1) * rsqrt(w*s2 + eps*w^2 - s1^2)   [floored at 1e-10]
//
// R12: each warp owns a 2048-element sub-segment end-to-end (own cp.async
// loads, own pass-1 rows, own pass-2 + coalesced store) with only syncwarp.
// The cross-warp affine prefix is a flag-chained relay through smem (warp w
// spins on warp w-1's publication; in-block spin is deadlock-free). The only
// __syncthreads is the flag-reset at kernel entry (graphs replay with stale
// smem). Math identical to R11: constant-weight pass-1 dot product and
// w-saturation split (w == 1.0f exactly for t0 >= 1792).

#define T_LEN  16384
#define TPB    256
#define KP     (T_LEN / TPB)     // 64 steps per thread
#define NWARP  (TPB / 32)        // 8
#define WSEG   (T_LEN / NWARP)   // 2048 floats per warp

#define ALPHA_F 0.99f
#define OMA_F   0.01f
#define EPS_F   1e-5f
#define A64_F   0.52559649f      // 0.99^64
#define W1_TID  28               // tid >= 28 -> t0 >= 1792 -> w == 1.0f

#define PAD(i)  ((i) + (((i) >> 6) << 2))      // +4 floats (16B) per 64-row
#define SMEM_F  (T_LEN + ((T_LEN >> 6) << 2))  // 17408 floats = 69632 B

__device__ __forceinline__ void cp_async16(float* smem_dst, const float* gmem_src) {
    uint32_t s = (uint32_t)__cvta_generic_to_shared(smem_dst);
    asm volatile("cp.async.cg.shared.global [%0], [%1], 16;" :: "r"(s), "l"(gmem_src));
}

__host__ __device__ constexpr float apow(int n) {
    float r = 1.0f;
    for (int i = 0; i < n; i++) r *= ALPHA_F;
    return r;
}

// pass-1 dot product, fully unrolled with constant weights; two accumulator
// pairs for ILP.  c_i = 0.01 * a^(KP-1-i).
template<int I>
__device__ __forceinline__ void warm_unroll(const float4* row,
                                            float& a0, float& b0,
                                            float& a1, float& b1) {
    if constexpr (I < KP / 4) {
        float4 v = row[I];
        constexpr float c0 = OMA_F * apow(KP - 1 - (4 * I + 0));
        constexpr float c1 = OMA_F * apow(KP - 1 - (4 * I + 1));
        constexpr float c2 = OMA_F * apow(KP - 1 - (4 * I + 2));
        constexpr float c3 = OMA_F * apow(KP - 1 - (4 * I + 3));
        float t0 = c0 * v.x;  a0 += t0;  b0 = fmaf(t0, v.x, b0);
        float t1 = c1 * v.y;  a1 += t1;  b1 = fmaf(t1, v.y, b1);
        float t2 = c2 * v.z;  a0 += t2;  b0 = fmaf(t2, v.z, b0);
        float t3 = c3 * v.w;  a1 += t3;  b1 = fmaf(t3, v.w, b1);
        warm_unroll<I + 1>(row, a0, b0, a1, b1);
    }
}

// full step: w still evolving (threads with t0 < 1792)
__device__ __forceinline__ float ema_step_w(float xi, float& s1, float& s2, float& w) {
    float t = OMA_F * xi;
    s1 = fmaf(ALPHA_F, s1, t);
    s2 = fmaf(ALPHA_F, s2, t * xi);
    w  = fmaf(ALPHA_F, w, OMA_F);
    float num = fmaf(w, xi, -s1);
    float e   = fmaf(EPS_F, w, s2);
    float d   = fmaf(w, e, -(s1 * s1));
    d = fmaxf(d, 1e-10f);
    float r;
    asm("rsqrt.approx.f32 %0, %1;" : "=f"(r) : "f"(d));
    return num * r;
}

// saturated step: w == 1.0f exactly
__device__ __forceinline__ float ema_step_1(float xi, float& s1, float& s2) {
    float t = OMA_F * xi;
    s1 = fmaf(ALPHA_F, s1, t);
    s2 = fmaf(ALPHA_F, s2, t * xi);
    float num = xi - s1;
    float e   = s2 + EPS_F;
    float d   = fmaf(-s1, s1, e);
    d = fmaxf(d, 1e-10f);
    float r;
    asm("rsqrt.approx.f32 %0, %1;" : "=f"(r) : "f"(d));
    return num * r;
}

extern __shared__ float s_buf[];

__global__ void __launch_bounds__(TPB)
ema_norm_kernel(const float* __restrict__ x, float* __restrict__ y)
{
    __shared__ volatile float pub1[NWARP], pub2[NWARP], pubm[NWARP];
    __shared__ volatile int   flag[NWARP];

    const int tid  = threadIdx.x;
    const int lane = tid & 31;
    const int wid  = tid >> 5;
    const size_t base = (size_t)blockIdx.x * T_LEN;

    // flags must be reset every launch (graph replays reuse stale smem)
    if (tid < NWARP) flag[tid] = 0;
    __syncthreads();                  // only block-wide barrier in the kernel

    // ---- warp-local async load of this warp's 2048-float segment ----
    const int wbase = wid * WSEG;     // float index of warp segment start
    #pragma unroll
    for (int k = 0; k < WSEG / (32 * 4); k++) {      // 16 iters
        int i4 = wbase + k * (32 * 4) + 4 * lane;    // 16B aligned
        cp_async16(s_buf + PAD(i4), x + base + i4);
    }
    asm volatile("cp.async.commit_group;");
    asm volatile("cp.async.wait_group 0;" ::: "memory");
    __syncwarp();                     // warp's own region fully visible

    // ---- pass 1: constant-weight segment sums (this warp's rows only) ----
    const int t0 = tid * KP;
    const float4* row = reinterpret_cast<const float4*>(s_buf + PAD(t0));
    float a0 = 0.f, b0 = 0.f, a1 = 0.f, b1 = 0.f;
    warm_unroll<0>(row, a0, b0, a1, b1);
    float L1 = a0 + a1;
    float L2 = b0 + b1;

    // ---- in-warp affine inclusive scan: combine = vR + mR*vL ----
    float v1 = L1, v2 = L2, m = A64_F;
    #pragma unroll
    for (int d = 1; d < 32; d <<= 1) {
        float pv1 = __shfl_up_sync(0xffffffffu, v1, d);
        float pv2 = __shfl_up_sync(0xffffffffu, v2, d);
        float pm  = __shfl_up_sync(0xffffffffu, m,  d);
        if (lane >= d) {
            v1 = fmaf(m, pv1, v1);
            v2 = fmaf(m, pv2, v2);
            m *= pm;
        }
    }
    float ev1 = __shfl_up_sync(0xffffffffu, v1, 1);
    float ev2 = __shfl_up_sync(0xffffffffu, v2, 1);
    float em  = __shfl_up_sync(0xffffffffu, m,  1);
    if (lane == 0) { ev1 = 0.f; ev2 = 0.f; em = 1.f; }

    // ---- cross-warp prefix: flag-chained relay through smem ----
    float p1 = 0.f, p2 = 0.f, pm = 1.f;
    if (wid > 0) {
        if (lane == 0) { while (flag[wid - 1] == 0) {} }
        __syncwarp();
        __threadfence_block();
        p1 = pub1[wid - 1]; p2 = pub2[wid - 1]; pm = pubm[wid - 1];
    }
    if (wid < NWARP - 1 && lane == 31) {
        // this warp's inclusive prefix = own total (v,m at lane31) ∘ prefix
        pub1[wid] = fmaf(m, p1, v1);
        pub2[wid] = fmaf(m, p2, v2);
        pubm[wid] = m * pm;
        __threadfence_block();
        flag[wid] = 1;
    }

    // thread's exact start state
    float s1 = fmaf(em, p1, ev1);
    float s2 = fmaf(em, p2, ev2);
    float w  = 1.0f - pm * em;        // == 1.0f exactly for tid >= 28

    // ---- pass 2: normalize 64 steps from exact state, in-place ----
    float4* rw = reinterpret_cast<float4*>(s_buf + PAD(t0));
    if (tid >= W1_TID) {
        #pragma unroll
        for (int i = 0; i < KP / 4; i++) {
            float4 v = rw[i];
            float4 o;
            o.x = ema_step_1(v.x, s1, s2);
            o.y = ema_step_1(v.y, s1, s2);
            o.z = ema_step_1(v.z, s1, s2);
            o.w = ema_step_1(v.w, s1, s2);
            rw[i] = o;
        }
    } else {
        #pragma unroll
        for (int i = 0; i < KP / 4; i++) {
            float4 v = rw[i];
            float4 o;
            o.x = ema_step_w(v.x, s1, s2, w);
            o.y = ema_step_w(v.y, s1, s2, w);
            o.z = ema_step_w(v.z, s1, s2, w);
            o.w = ema_step_w(v.w, s1, s2, w);
            rw[i] = o;
        }
    }
    __syncwarp();                     // warp's region fully written

    // ---- warp-local coalesced store of this warp's segment ----
    #pragma unroll
    for (int k = 0; k < WSEG / (32 * 4); k++) {
        int i4 = wbase + k * (32 * 4) + 4 * lane;
        float4 v = *reinterpret_cast<const float4*>(s_buf + PAD(i4));
        *reinterpret_cast<float4*>(y + base + i4) = v;
    }
}

extern "C" void kernel_launch(void* const* d_in, const int* in_sizes, int n_in,
                              void* d_out, int out_size) {
    const float* x = (const float*)d_in[0];
    float*       y = (float*)d_out;

    int total = in_sizes[0];            // B*C*T
    int lanes = total / T_LEN;          // 2048 blocks, one per lane

    cudaFuncSetAttribute(ema_norm_kernel,
                         cudaFuncAttributeMaxDynamicSharedMemorySize,
                         SMEM_F * sizeof(float));
    ema_norm_kernel<<<lanes, TPB, SMEM_F * sizeof(float)>>>(x, y);
}